// round 9
// baseline (speedup 1.0000x reference)
#include <cuda_runtime.h>
#include <math.h>

// BaseRoIHead multi-level RoIAlign (torchvision-style, aligned=False)
// B=2, R=512, C=256, out 7x7, sampling_ratio=2, levels p2..p6 (strides 4..64).
//
//  - one CTA per (roi, out-row): grid (1024, 7), 64 threads = 1 float4 group
//  - branchless bilinear: validity + 0.25 mean folded into shared weights
//  - y-tap rows deduplicated at setup (separable outer product lets duplicate
//    rows merge by summing weights); one uniform branch selects a fully
//    unrolled 2/3/4-row body -> 8/12/16 loads per bin

#define OUT_HW 7
#define NS (OUT_HW * 2)    // 14 x-sample coords
#define CCH 256
#define CG  (CCH / 4)      // 64 float4 channel groups

__device__ __forceinline__ float4 f4fma(float s, float4 v, float4 a) {
    a.x = fmaf(s, v.x, a.x); a.y = fmaf(s, v.y, a.y);
    a.z = fmaf(s, v.z, a.z); a.w = fmaf(s, v.w, a.w);
    return a;
}

// NR unique y-rows, 4 x-taps per bin, fully unrolled.
template <int NR>
__device__ __forceinline__ void row_body(
    const float* __restrict__ r0, const float* __restrict__ r1,
    const float* __restrict__ r2, const float* __restrict__ r3,
    float wy0, float wy1, float wy2, float wy3,
    const int* __restrict__ s_xoa, const int* __restrict__ s_xob,
    const float* __restrict__ s_hx, const float* __restrict__ s_lx,
    float* __restrict__ orow)
{
    #pragma unroll
    for (int ow = 0; ow < OUT_HW; ow++) {
        const int j0 = ow * 2, j1 = ow * 2 + 1;
        const int oa0 = s_xoa[j0], ob0 = s_xob[j0];
        const int oa1 = s_xoa[j1], ob1 = s_xob[j1];
        const float hx0 = s_hx[j0], lx0 = s_lx[j0];
        const float hx1 = s_hx[j1], lx1 = s_lx[j1];

        float4 acc = make_float4(0.f, 0.f, 0.f, 0.f);
        {
            float4 a = *(const float4*)(r0 + oa0);
            float4 bq = *(const float4*)(r0 + ob0);
            float4 c = *(const float4*)(r0 + oa1);
            float4 d = *(const float4*)(r0 + ob1);
            acc = f4fma(wy0 * hx0, a, acc);
            acc = f4fma(wy0 * lx0, bq, acc);
            acc = f4fma(wy0 * hx1, c, acc);
            acc = f4fma(wy0 * lx1, d, acc);
        }
        {
            float4 a = *(const float4*)(r1 + oa0);
            float4 bq = *(const float4*)(r1 + ob0);
            float4 c = *(const float4*)(r1 + oa1);
            float4 d = *(const float4*)(r1 + ob1);
            acc = f4fma(wy1 * hx0, a, acc);
            acc = f4fma(wy1 * lx0, bq, acc);
            acc = f4fma(wy1 * hx1, c, acc);
            acc = f4fma(wy1 * lx1, d, acc);
        }
        if (NR > 2) {
            float4 a = *(const float4*)(r2 + oa0);
            float4 bq = *(const float4*)(r2 + ob0);
            float4 c = *(const float4*)(r2 + oa1);
            float4 d = *(const float4*)(r2 + ob1);
            acc = f4fma(wy2 * hx0, a, acc);
            acc = f4fma(wy2 * lx0, bq, acc);
            acc = f4fma(wy2 * hx1, c, acc);
            acc = f4fma(wy2 * lx1, d, acc);
        }
        if (NR > 3) {
            float4 a = *(const float4*)(r3 + oa0);
            float4 bq = *(const float4*)(r3 + ob0);
            float4 c = *(const float4*)(r3 + oa1);
            float4 d = *(const float4*)(r3 + ob1);
            acc = f4fma(wy3 * hx0, a, acc);
            acc = f4fma(wy3 * lx0, bq, acc);
            acc = f4fma(wy3 * hx1, c, acc);
            acc = f4fma(wy3 * lx1, d, acc);
        }
        *(float4*)(orow + ow * CCH) = acc;
    }
}

__global__ __launch_bounds__(CG, 18) void roialign_fpn_kernel(
    const float* __restrict__ p2, const float* __restrict__ p3,
    const float* __restrict__ p4, const float* __restrict__ p5,
    const float* __restrict__ p6, const float* __restrict__ proposals,
    float* __restrict__ out)
{
    const int roi = blockIdx.x;          // b * 512 + r
    const int oh  = blockIdx.y;          // output row 0..6
    const int b   = roi >> 9;
    const int tx  = threadIdx.x;         // 0..63 channel group

    __shared__ int   s_xoa[NS], s_xob[NS];     // x-tap element offsets
    __shared__ float s_hx[NS], s_lx[NS];       // masked x weights
    __shared__ int   s_rowoff[4];              // deduped row elem offsets (padded)
    __shared__ float s_wy[4];                  // merged y weights * 0.25
    __shared__ int   s_nrows;
    __shared__ const float* s_feat;

    if (tx < 32) {
        // uniform box/level scalars computed by every lane
        const float* box = proposals + (size_t)roi * 4;
        float bx1 = box[0], by1 = box[1], bx2 = box[2], by2 = box[3];

        float w = fmaxf(bx2 - bx1, 1.0f);
        float h = fmaxf(by2 - by1, 1.0f);
        float lvlf = floorf(4.0f + log2f(sqrtf(w * h) / 224.0f));
        int lvl = (int)fminf(fmaxf(lvlf, 2.0f), 6.0f);   // 2..6

        int H = 1024 >> lvl;
        float Hf = (float)H;
        float scale = 1.0f / (float)(1 << lvl);

        float x1s = bx1 * scale, y1s = by1 * scale;
        float bin_w = fmaxf(bx2 * scale - x1s, 1.0f) / (float)OUT_HW;
        float bin_h = fmaxf(by2 * scale - y1s, 1.0f) / (float)OUT_HW;

        if (tx < NS) {
            // lanes 0..13: one x-sample each
            const int j = tx;
            float pos = (float)(j >> 1) + ((float)(j & 1) + 0.5f) * 0.5f;
            float X = x1s + pos * bin_w;
            bool ok = (X >= -1.0f) && (X <= Hf);
            float x = fminf(fmaxf(X, 0.0f), Hf - 1.0f);
            float x0 = floorf(x);
            int xa = (int)x0;
            int xb = min(xa + 1, H - 1);
            float lx = x - x0;
            s_xoa[j] = xa * CCH;
            s_xob[j] = xb * CCH;
            s_hx[j] = ok ? (1.0f - lx) : 0.0f;
            s_lx[j] = ok ? lx : 0.0f;
        } else if (tx == 16) {
            // lane 16: both y-samples of this row + duplicate-row merge
            int   ro[4];
            float wv[4];
            #pragma unroll
            for (int k = 0; k < 2; k++) {
                const int iy = oh * 2 + k;
                float pos = (float)(iy >> 1) + ((float)(iy & 1) + 0.5f) * 0.5f;
                float Y = y1s + pos * bin_h;
                bool ok = (Y >= -1.0f) && (Y <= Hf);
                float y = fminf(fmaxf(Y, 0.0f), Hf - 1.0f);
                float y0 = floorf(y);
                int ya = (int)y0;
                int yb = min(ya + 1, H - 1);
                float ly = y - y0;
                ro[2 * k]     = ya * H * CCH;
                ro[2 * k + 1] = yb * H * CCH;
                wv[2 * k]     = ok ? (1.0f - ly) * 0.25f : 0.0f;
                wv[2 * k + 1] = ok ? ly * 0.25f : 0.0f;
            }
            // merge duplicates (separable outer product -> weights add)
            int   mo[4];
            float mw[4];
            int n = 0;
            #pragma unroll
            for (int t = 0; t < 4; t++) {
                bool found = false;
                #pragma unroll
                for (int u = 0; u < 4; u++) {
                    if (u < n && mo[u] == ro[t] && !found) {
                        mw[u] += wv[t];
                        found = true;
                    }
                }
                if (!found) { mo[n] = ro[t]; mw[n] = wv[t]; n++; }
            }
            #pragma unroll
            for (int u = 0; u < 4; u++) {
                if (u >= n) { mo[u] = mo[0]; mw[u] = 0.0f; }
                s_rowoff[u] = mo[u];
                s_wy[u] = mw[u];
            }
            s_nrows = n;
        } else if (tx == 31) {
            const float* feats[5] = {p2, p3, p4, p5, p6};
            s_feat = feats[lvl - 2] + (size_t)b * H * H * CCH;
        }
    }
    __syncthreads();

    const int cb = tx * 4;
    const float* base = s_feat + cb;
    const float* r0 = base + s_rowoff[0];
    const float* r1 = base + s_rowoff[1];
    const float* r2 = base + s_rowoff[2];
    const float* r3 = base + s_rowoff[3];
    const float wy0 = s_wy[0], wy1 = s_wy[1], wy2 = s_wy[2], wy3 = s_wy[3];
    const int nr = s_nrows;

    float* orow = out + ((size_t)roi * (OUT_HW * OUT_HW) + oh * OUT_HW) * CCH + cb;

    if (nr == 4) {
        row_body<4>(r0, r1, r2, r3, wy0, wy1, wy2, wy3,
                    s_xoa, s_xob, s_hx, s_lx, orow);
    } else if (nr == 3) {
        row_body<3>(r0, r1, r2, r3, wy0, wy1, wy2, wy3,
                    s_xoa, s_xob, s_hx, s_lx, orow);
    } else {
        row_body<2>(r0, r1, r2, r3, wy0, wy1, wy2, wy3,
                    s_xoa, s_xob, s_hx, s_lx, orow);
    }
}

extern "C" void kernel_launch(void* const* d_in, const int* in_sizes, int n_in,
                              void* d_out, int out_size) {
    // Identify inputs by element count (all distinct):
    // p2=33554432, p3=8388608, p4=2097152, p5=524288, p6=131072, proposals=4096
    const float* ptr[6] = {nullptr, nullptr, nullptr, nullptr, nullptr, nullptr};
    int num_rois = 1024;
    for (int i = 0; i < n_in && i < 6; i++) {
        switch (in_sizes[i]) {
            case 33554432: ptr[0] = (const float*)d_in[i]; break;  // p2
            case 8388608:  ptr[1] = (const float*)d_in[i]; break;  // p3
            case 2097152:  ptr[2] = (const float*)d_in[i]; break;  // p4
            case 524288:   ptr[3] = (const float*)d_in[i]; break;  // p5
            case 131072:   ptr[4] = (const float*)d_in[i]; break;  // p6
            default:       ptr[5] = (const float*)d_in[i];
                           num_rois = in_sizes[i] / 4;     break;  // proposals
        }
    }

    dim3 grid(num_rois, OUT_HW, 1);
    roialign_fpn_kernel<<<grid, CG>>>(ptr[0], ptr[1], ptr[2], ptr[3],
                                      ptr[4], ptr[5], (float*)d_out);
}